// round 1
// baseline (speedup 1.0000x reference)
#include <cuda_runtime.h>
#include <cstddef>

// ---------------------------------------------------------------------------
// Problem constants (padded capacities for static scratch)
// ---------------------------------------------------------------------------
#define NMAX 50048          // >= 49998
#define EMAX 1000064        // >= 800000
#define H0 8
#define DOUT 32
#define F0DIM (H0*DOUT)     // 256

// ---------------------------------------------------------------------------
// Static device scratch (allocation-free rule: __device__ globals)
// ---------------------------------------------------------------------------
__device__ float g_f0[(size_t)NMAX * F0DIM];   // layer-0 projected features
__device__ float g_h0[(size_t)NMAX * F0DIM];   // layer-0 output (after elu)
__device__ float g_f1[(size_t)NMAX * DOUT];    // layer-1 projected features
__device__ float g_h1[(size_t)NMAX * DOUT];    // layer-1 output
__device__ float g_el0[(size_t)NMAX * H0];
__device__ float g_er0[(size_t)NMAX * H0];
__device__ float g_el1[NMAX];
__device__ float g_er1[NMAX];
__device__ int   g_cnt[NMAX];
__device__ int   g_rowptr[NMAX + 1];
__device__ int   g_cursor[NMAX];
__device__ int   g_csrc[EMAX];
__device__ int   g_bsums[256];

// ---------------------------------------------------------------------------
// CSR construction: zero -> histogram -> scan (3 kernels) -> cursor -> fill
// ---------------------------------------------------------------------------
__global__ void k_zero_cnt(int N) {
    int i = blockIdx.x * blockDim.x + threadIdx.x;
    if (i < N) g_cnt[i] = 0;
}

__global__ void k_hist(const int* __restrict__ dst, int E) {
    int e = blockIdx.x * blockDim.x + threadIdx.x;
    if (e < E) atomicAdd(&g_cnt[dst[e]], 1);
}

// per-block inclusive scan of g_cnt -> g_rowptr[i+1]; block sum -> g_bsums[b]
__global__ void k_scanA(int N) {
    __shared__ int s[256];
    int t = threadIdx.x;
    int idx = blockIdx.x * 256 + t;
    int v = (idx < N) ? g_cnt[idx] : 0;
    s[t] = v;
    __syncthreads();
    for (int off = 1; off < 256; off <<= 1) {
        int u = 0;
        if (t >= off) u = s[t - off];
        __syncthreads();
        if (t >= off) s[t] += u;
        __syncthreads();
    }
    if (idx < N) g_rowptr[idx + 1] = s[t];
    if (t == 255) g_bsums[blockIdx.x] = s[255];
}

// single-block exclusive scan of block sums (nb <= 256)
__global__ void k_scanB(int nb) {
    __shared__ int s[256];
    int t = threadIdx.x;
    int v = (t < nb) ? g_bsums[t] : 0;
    s[t] = v;
    __syncthreads();
    for (int off = 1; off < 256; off <<= 1) {
        int u = 0;
        if (t >= off) u = s[t - off];
        __syncthreads();
        if (t >= off) s[t] += u;
        __syncthreads();
    }
    if (t < nb) g_bsums[t] = s[t] - v;   // exclusive
}

__global__ void k_scanC(int N) {
    int idx = blockIdx.x * blockDim.x + threadIdx.x;
    if (idx < N) g_rowptr[idx + 1] += g_bsums[idx >> 8];
    if (idx == 0) g_rowptr[0] = 0;
}

__global__ void k_cursor(int N) {
    int i = blockIdx.x * blockDim.x + threadIdx.x;
    if (i < N) g_cursor[i] = g_rowptr[i];
}

__global__ void k_fill(const int* __restrict__ src, const int* __restrict__ dst, int E) {
    int e = blockIdx.x * blockDim.x + threadIdx.x;
    if (e < E) {
        int p = atomicAdd(&g_cursor[dst[e]], 1);
        g_csrc[p] = src[e];
    }
}

// ---------------------------------------------------------------------------
// Tiled fp32 GEMM: C[M,N] = A[M,K] @ B[K,N].  BM=64 BN=32 BK=16, 128 thr, 4x4
// Requirements: K % 16 == 0, N % 32 == 0 (holds: K in {128,256}, N in {256,32})
// ---------------------------------------------------------------------------
__global__ __launch_bounds__(128) void k_gemm(const float* __restrict__ A,
                                              const float* __restrict__ B,
                                              float* __restrict__ C,
                                              int M, int N, int K) {
    __shared__ float As[16][64];
    __shared__ float Bs[16][32];
    int tid = threadIdx.x;
    int tx = tid & 7;    // 0..7  (col group * 4)
    int ty = tid >> 3;   // 0..15 (row group * 4)
    int m0 = blockIdx.y * 64;
    int n0 = blockIdx.x * 32;
    float acc[4][4];
#pragma unroll
    for (int i = 0; i < 4; i++)
#pragma unroll
        for (int j = 0; j < 4; j++) acc[i][j] = 0.f;

    for (int k0 = 0; k0 < K; k0 += 16) {
#pragma unroll
        for (int q = 0; q < 2; q++) {
            int l = tid + q * 128;       // 0..255 float4 slots of the 64x16 tile
            int m = l >> 2;              // 0..63
            int kq = (l & 3) * 4;        // 0,4,8,12
            float4 v = make_float4(0.f, 0.f, 0.f, 0.f);
            if (m0 + m < M)
                v = *(const float4*)(A + (size_t)(m0 + m) * K + k0 + kq);
            As[kq + 0][m] = v.x; As[kq + 1][m] = v.y;
            As[kq + 2][m] = v.z; As[kq + 3][m] = v.w;
        }
        {
            int kk = tid >> 3;           // 0..15
            int nq = (tid & 7) * 4;      // 0..28
            float4 v = *(const float4*)(B + (size_t)(k0 + kk) * N + n0 + nq);
            *(float4*)&Bs[kk][nq] = v;
        }
        __syncthreads();
#pragma unroll
        for (int kk = 0; kk < 16; kk++) {
            float4 a4 = *(const float4*)&As[kk][ty * 4];
            float4 b4 = *(const float4*)&Bs[kk][tx * 4];
            float a[4] = {a4.x, a4.y, a4.z, a4.w};
            float b[4] = {b4.x, b4.y, b4.z, b4.w};
#pragma unroll
            for (int i = 0; i < 4; i++)
#pragma unroll
                for (int j = 0; j < 4; j++) acc[i][j] += a[i] * b[j];
        }
        __syncthreads();
    }
#pragma unroll
    for (int i = 0; i < 4; i++) {
        int m = m0 + ty * 4 + i;
        if (m < M) {
#pragma unroll
            for (int j = 0; j < 4; j++)
                C[(size_t)m * N + n0 + tx * 4 + j] = acc[i][j];
        }
    }
}

// ---------------------------------------------------------------------------
// Attention scalars: el[i,h] = dot(f[i,h,:], al[h,:]), er likewise.
// One warp per (node, head), lane = feature dim.
// ---------------------------------------------------------------------------
__global__ void k_scores(const float* __restrict__ f,
                         const float* __restrict__ al,
                         const float* __restrict__ ar,
                         float* __restrict__ el, float* __restrict__ er,
                         int N, int H) {
    int w = (blockIdx.x * blockDim.x + threadIdx.x) >> 5;
    int lane = threadIdx.x & 31;
    if (w >= N * H) return;
    int i = w / H, h = w % H;
    float v = f[(size_t)i * (H * DOUT) + h * DOUT + lane];
    float a = v * al[h * DOUT + lane];
    float b = v * ar[h * DOUT + lane];
#pragma unroll
    for (int off = 16; off; off >>= 1) {
        a += __shfl_down_sync(0xffffffffu, a, off);
        b += __shfl_down_sync(0xffffffffu, b, off);
    }
    if (lane == 0) { el[i * H + h] = a; er[i * H + h] = b; }
}

// ---------------------------------------------------------------------------
// Pull-style GAT aggregation over CSR.  Warp per (node, head), lane = dim.
// softmax without max-shift (scores are O(1); mathematically identical ratio)
// ---------------------------------------------------------------------------
__global__ void k_aggregate(const float* __restrict__ f,
                            const float* __restrict__ el,
                            const float* __restrict__ er,
                            const float* __restrict__ bias,
                            float* __restrict__ out,
                            int N, int H, int apply_elu) {
    int w = (blockIdx.x * blockDim.x + threadIdx.x) >> 5;
    int lane = threadIdx.x & 31;
    if (w >= N * H) return;
    int i = w / H, h = w % H;
    int s0 = g_rowptr[i], s1 = g_rowptr[i + 1];
    float er_i = er[i * H + h];
    float denom = 0.f, acc = 0.f;
    for (int j = s0; j < s1; j++) {
        int s = g_csrc[j];
        float e = el[s * H + h] + er_i;
        e = (e > 0.f) ? e : 0.2f * e;         // leaky_relu(0.2)
        float a = __expf(e);
        denom += a;
        acc += a * f[(size_t)s * (H * DOUT) + h * DOUT + lane];
    }
    float o = (s1 > s0) ? (acc / denom) : 0.f;
    o += bias[h * DOUT + lane];
    if (apply_elu) o = (o > 0.f) ? o : (__expf(o) - 1.f);
    out[(size_t)i * (H * DOUT) + h * DOUT + lane] = o;
}

// ---------------------------------------------------------------------------
// Link predictor: z=src*dst elementwise (32), MLP 32->32(relu)->32(relu)->1.
// Warp per row; weights in shared; shuffle-broadcast matvec.
// ---------------------------------------------------------------------------
__global__ void k_predictor(const float* __restrict__ h,
                            const int* __restrict__ ratio_ptr,
                            const float* __restrict__ P1, const float* __restrict__ pb1,
                            const float* __restrict__ P2, const float* __restrict__ pb2,
                            const float* __restrict__ P3, const float* __restrict__ pb3,
                            float* __restrict__ out, int N) {
    __shared__ float sP1[32 * 32], sP2[32 * 32], sP3[32], sb1[32], sb2[32];
    __shared__ float sb3;
    int t = threadIdx.x;
    for (int idx = t; idx < 1024; idx += blockDim.x) {
        sP1[idx] = P1[idx];
        sP2[idx] = P2[idx];
    }
    if (t < 32) { sP3[t] = P3[t]; sb1[t] = pb1[t]; sb2[t] = pb2[t]; }
    if (t == 0) sb3 = pb3[0];
    __syncthreads();

    int ratio = *ratio_ptr;
    int ne = N / (ratio + 2);
    int R = (1 + ratio) * ne;
    int lane = t & 31;
    int wpb = blockDim.x >> 5;
    for (int r = blockIdx.x * wpb + (t >> 5); r < R; r += gridDim.x * wpb) {
        int ia, ib, oi;
        if (r < ne) { ia = r; ib = r + ne; oi = r; }
        else {
            int j = r - ne;
            ia = j % ne; ib = 2 * ne + j; oi = ne + j;
        }
        float z = h[(size_t)ia * DOUT + lane] * h[(size_t)ib * DOUT + lane];

        float z1 = sb1[lane];
#pragma unroll
        for (int k = 0; k < 32; k++)
            z1 += __shfl_sync(0xffffffffu, z, k) * sP1[k * 32 + lane];
        z1 = fmaxf(z1, 0.f);

        float z2 = sb2[lane];
#pragma unroll
        for (int k = 0; k < 32; k++)
            z2 += __shfl_sync(0xffffffffu, z1, k) * sP2[k * 32 + lane];
        z2 = fmaxf(z2, 0.f);

        float v = z2 * sP3[lane];
#pragma unroll
        for (int off = 16; off; off >>= 1)
            v += __shfl_down_sync(0xffffffffu, v, off);
        if (lane == 0) out[oi] = v + sb3;
    }
}

// ---------------------------------------------------------------------------
// Launch
// ---------------------------------------------------------------------------
extern "C" void kernel_launch(void* const* d_in, const int* in_sizes, int n_in,
                              void* d_out, int out_size) {
    const float* x    = (const float*)d_in[0];
    const int*   src  = (const int*)d_in[1];
    const int*   dst  = (const int*)d_in[2];
    const int*   nsr  = (const int*)d_in[3];
    const float* W0   = (const float*)d_in[4];
    const float* al0  = (const float*)d_in[5];
    const float* ar0  = (const float*)d_in[6];
    const float* b0   = (const float*)d_in[7];
    const float* W1   = (const float*)d_in[8];
    const float* al1  = (const float*)d_in[9];
    const float* ar1  = (const float*)d_in[10];
    const float* b1   = (const float*)d_in[11];
    const float* P1   = (const float*)d_in[12];
    const float* pb1  = (const float*)d_in[13];
    const float* P2   = (const float*)d_in[14];
    const float* pb2  = (const float*)d_in[15];
    const float* P3   = (const float*)d_in[16];
    const float* pb3  = (const float*)d_in[17];
    float* out = (float*)d_out;

    int N = in_sizes[0] / 128;   // DIM_IN = 128
    int E = in_sizes[1];

    float *p_f0, *p_h0, *p_f1, *p_h1, *p_el0, *p_er0, *p_el1, *p_er1;
    cudaGetSymbolAddress((void**)&p_f0,  g_f0);
    cudaGetSymbolAddress((void**)&p_h0,  g_h0);
    cudaGetSymbolAddress((void**)&p_f1,  g_f1);
    cudaGetSymbolAddress((void**)&p_h1,  g_h1);
    cudaGetSymbolAddress((void**)&p_el0, g_el0);
    cudaGetSymbolAddress((void**)&p_er0, g_er0);
    cudaGetSymbolAddress((void**)&p_el1, g_el1);
    cudaGetSymbolAddress((void**)&p_er1, g_er1);

    int nbN = (N + 255) / 256;
    int nbE = (E + 255) / 256;

    // --- CSR build (by dst) ---
    k_zero_cnt<<<nbN, 256>>>(N);
    k_hist<<<nbE, 256>>>(dst, E);
    k_scanA<<<nbN, 256>>>(N);
    k_scanB<<<1, 256>>>(nbN);
    k_scanC<<<nbN, 256>>>(N);
    k_cursor<<<nbN, 256>>>(N);
    k_fill<<<nbE, 256>>>(src, dst, E);

    // --- layer 0: f0 = x @ W0 ; scores ; aggregate (+elu) ---
    {
        dim3 grid((F0DIM + 31) / 32, (N + 63) / 64);
        k_gemm<<<grid, 128>>>(x, W0, p_f0, N, F0DIM, 128);
    }
    {
        long warps = (long)N * H0;
        int blocks = (int)((warps * 32 + 255) / 256);
        k_scores<<<blocks, 256>>>(p_f0, al0, ar0, p_el0, p_er0, N, H0);
        k_aggregate<<<blocks, 256>>>(p_f0, p_el0, p_er0, b0, p_h0, N, H0, 1);
    }

    // --- layer 1: f1 = h0 @ W1 ; scores ; aggregate ---
    {
        dim3 grid((DOUT + 31) / 32, (N + 63) / 64);
        k_gemm<<<grid, 128>>>(p_h0, W1, p_f1, N, DOUT, F0DIM);
    }
    {
        long warps = (long)N;
        int blocks = (int)((warps * 32 + 255) / 256);
        k_scores<<<blocks, 256>>>(p_f1, al1, ar1, p_el1, p_er1, N, 1);
        k_aggregate<<<blocks, 256>>>(p_f1, p_el1, p_er1, b1, p_h1, N, 1, 0);
    }

    // --- predictor ---
    k_predictor<<<512, 256>>>(p_h1, nsr, P1, pb1, P2, pb2, P3, pb3, out, N);
}

// round 2
// speedup vs baseline: 1.1536x; 1.1536x over previous
#include <cuda_runtime.h>
#include <cstdint>
#include <cstddef>

// ---------------------------------------------------------------------------
// Problem constants (padded capacities for static scratch)
// ---------------------------------------------------------------------------
#define NMAX 50048
#define EMAX 1000064
#define H0 8
#define DOUT 32
#define F0DIM (H0*DOUT)     // 256

// ---------------------------------------------------------------------------
// Static device scratch
// ---------------------------------------------------------------------------
__device__ float g_f0[(size_t)NMAX * F0DIM];
__device__ float g_h0[(size_t)NMAX * F0DIM];
__device__ float g_f1[(size_t)NMAX * DOUT];
__device__ float g_h1[(size_t)NMAX * DOUT];
__device__ float g_el0[(size_t)NMAX * H0];
__device__ float g_er0[(size_t)NMAX * H0];
__device__ float g_el1[NMAX];
__device__ float g_er1[NMAX];
__device__ int   g_cnt[NMAX];
__device__ int   g_rowptr[NMAX + 1];
__device__ int   g_cursor[NMAX];
__device__ int   g_csrc[EMAX];

// ---------------------------------------------------------------------------
// CSR build: zero -> histogram -> single-block scan -> fill   (4 launches)
// ---------------------------------------------------------------------------
__global__ void k_zero_cnt(int N) {
    int i = blockIdx.x * blockDim.x + threadIdx.x;
    if (i < N) g_cnt[i] = 0;
}

__global__ void k_hist(const int* __restrict__ dst, int E) {
    int e = blockIdx.x * blockDim.x + threadIdx.x;
    if (e < E) atomicAdd(&g_cnt[dst[e]], 1);
}

// single-block scan of g_cnt -> exclusive g_rowptr[0..N], cursor copy
__global__ void k_scan(int N) {
    __shared__ int s[1024];
    int t = threadIdx.x;
    int C = (N + 1023) / 1024;
    int beg = t * C;
    int end = beg + C; if (end > N) end = N;
    int sum = 0;
    for (int i = beg; i < end; i++) sum += g_cnt[i];
    s[t] = sum;
    __syncthreads();
    for (int off = 1; off < 1024; off <<= 1) {
        int u = (t >= off) ? s[t - off] : 0;
        __syncthreads();
        if (t >= off) s[t] += u;
        __syncthreads();
    }
    int pre = (t == 0) ? 0 : s[t - 1];
    for (int i = beg; i < end; i++) {
        int c = g_cnt[i];
        g_rowptr[i] = pre;
        g_cursor[i] = pre;
        pre += c;
    }
    if (t == 1023) g_rowptr[N] = s[1023];
}

__global__ void k_fill(const int* __restrict__ src, const int* __restrict__ dst, int E) {
    int e = blockIdx.x * blockDim.x + threadIdx.x;
    if (e < E) {
        int p = atomicAdd(&g_cursor[dst[e]], 1);
        g_csrc[p] = src[e];
    }
}

// ---------------------------------------------------------------------------
// TF32 tensor-core GEMM with fused attention-score epilogue.
// C[M,N] = A[M,K] @ B[K,N]; per head h (=32 cols): el[m,h]=dot(C row seg, al),
// er likewise.  BM=128, BK=32, 256 threads.
// Template: BN (block cols), WMI x WNI warp grid (WMI*WNI == 8).
// ---------------------------------------------------------------------------
__device__ __forceinline__ uint32_t f2tf32(float v) {
    uint32_t u;
    asm("cvt.rna.tf32.f32 %0, %1;" : "=r"(u) : "f"(v));
    return u;
}

template<int BN, int WMI, int WNI>
__global__ __launch_bounds__(256) void k_gemm_tf32(
    const float* __restrict__ A, const float* __restrict__ B,
    float* __restrict__ C,
    const float* __restrict__ al, const float* __restrict__ ar,
    float* __restrict__ el, float* __restrict__ er,
    int M, int N, int K, int H)
{
    constexpr int BM = 128;
    constexpr int BK = 32;
    constexpr int WM = BM / WMI;          // rows per warp
    constexpr int WN = BN / WNI;          // cols per warp
    constexpr int MFR = WM / 16;
    constexpr int NFR = WN / 8;
    constexpr int HW  = (WN + 31) / 32;   // heads per warp (>=1)
    constexpr int AS_STRIDE = 36;         // 128 k-pad
    constexpr int BS_STRIDE = BN + 8;

    __shared__ uint32_t As[BM * AS_STRIDE];
    __shared__ uint32_t Bs[BK * BS_STRIDE];

    int tid = threadIdx.x;
    int lane = tid & 31;
    int w = tid >> 5;
    int warp_m = w % WMI;
    int warp_n = w / WMI;
    int m0 = blockIdx.y * BM;
    int n0 = blockIdx.x * BN;
    int wr = warp_m * WM;                 // warp row base (block-local)

    float c[MFR][NFR][4];
#pragma unroll
    for (int i = 0; i < MFR; i++)
#pragma unroll
        for (int j = 0; j < NFR; j++)
#pragma unroll
            for (int q = 0; q < 4; q++) c[i][j][q] = 0.f;

    for (int k0 = 0; k0 < K; k0 += BK) {
        // --- load A tile (BM x BK) ---
#pragma unroll
        for (int q = 0; q < (BM * BK / 4) / 256; q++) {
            int idx = tid + q * 256;
            int row = idx >> 3;           // BK/4 = 8 float4 per row
            int c4  = idx & 7;
            uint4 u = make_uint4(0u, 0u, 0u, 0u);
            int grow = m0 + row;
            if (grow < M) {
                float4 v = *(const float4*)(A + (size_t)grow * K + k0 + c4 * 4);
                u.x = f2tf32(v.x); u.y = f2tf32(v.y);
                u.z = f2tf32(v.z); u.w = f2tf32(v.w);
            }
            *(uint4*)&As[row * AS_STRIDE + c4 * 4] = u;
        }
        // --- load B tile (BK x BN) ---
#pragma unroll
        for (int q = 0; q < (BK * BN / 4) / 256; q++) {
            int idx = tid + q * 256;
            int row = idx / (BN / 4);
            int c4  = idx % (BN / 4);
            float4 v = *(const float4*)(B + (size_t)(k0 + row) * N + n0 + c4 * 4);
            uint4 u;
            u.x = f2tf32(v.x); u.y = f2tf32(v.y);
            u.z = f2tf32(v.z); u.w = f2tf32(v.w);
            *(uint4*)&Bs[row * BS_STRIDE + c4 * 4] = u;
        }
        __syncthreads();

#pragma unroll
        for (int kk = 0; kk < BK; kk += 8) {
            uint32_t af[MFR][4];
#pragma unroll
            for (int mf = 0; mf < MFR; mf++) {
                int r = wr + mf * 16 + (lane >> 2);
                int kc = kk + (lane & 3);
                af[mf][0] = As[r * AS_STRIDE + kc];
                af[mf][1] = As[(r + 8) * AS_STRIDE + kc];
                af[mf][2] = As[r * AS_STRIDE + kc + 4];
                af[mf][3] = As[(r + 8) * AS_STRIDE + kc + 4];
            }
            uint32_t bf[NFR][2];
#pragma unroll
            for (int nf = 0; nf < NFR; nf++) {
                int n = warp_n * WN + nf * 8 + (lane >> 2);
                int kc = kk + (lane & 3);
                bf[nf][0] = Bs[kc * BS_STRIDE + n];
                bf[nf][1] = Bs[(kc + 4) * BS_STRIDE + n];
            }
#pragma unroll
            for (int mf = 0; mf < MFR; mf++)
#pragma unroll
                for (int nf = 0; nf < NFR; nf++) {
                    asm volatile(
                        "mma.sync.aligned.m16n8k8.row.col.f32.tf32.tf32.f32 "
                        "{%0,%1,%2,%3}, {%4,%5,%6,%7}, {%8,%9}, {%0,%1,%2,%3};\n"
                        : "+f"(c[mf][nf][0]), "+f"(c[mf][nf][1]),
                          "+f"(c[mf][nf][2]), "+f"(c[mf][nf][3])
                        : "r"(af[mf][0]), "r"(af[mf][1]), "r"(af[mf][2]), "r"(af[mf][3]),
                          "r"(bf[nf][0]), "r"(bf[nf][1]));
                }
        }
        __syncthreads();
    }

    // --- epilogue: store C, accumulate per-head score dots ---
    float elp[MFR][2][HW], erp[MFR][2][HW];
#pragma unroll
    for (int mf = 0; mf < MFR; mf++)
#pragma unroll
        for (int hf = 0; hf < 2; hf++)
#pragma unroll
            for (int hh = 0; hh < HW; hh++) { elp[mf][hf][hh] = 0.f; erp[mf][hf][hh] = 0.f; }

#pragma unroll
    for (int nf = 0; nf < NFR; nf++) {
        int colb = warp_n * WN + nf * 8;             // block-local col base
        int hw = (nf * 8) >> 5;                      // head within warp
        int hg = (n0 + colb) >> 5;                   // global head
        int ch = (colb & 31) + 2 * (lane & 3);       // col within head
        float av0 = al[hg * 32 + ch], av1 = al[hg * 32 + ch + 1];
        float rv0 = ar[hg * 32 + ch], rv1 = ar[hg * 32 + ch + 1];
        int gcol = n0 + colb + 2 * (lane & 3);
#pragma unroll
        for (int mf = 0; mf < MFR; mf++) {
            int r0 = m0 + wr + mf * 16 + (lane >> 2);
            int r1 = r0 + 8;
            float c0 = c[mf][nf][0], c1 = c[mf][nf][1];
            float c2 = c[mf][nf][2], c3 = c[mf][nf][3];
            if (r0 < M) *(float2*)(C + (size_t)r0 * N + gcol) = make_float2(c0, c1);
            if (r1 < M) *(float2*)(C + (size_t)r1 * N + gcol) = make_float2(c2, c3);
            elp[mf][0][hw] += c0 * av0 + c1 * av1;
            elp[mf][1][hw] += c2 * av0 + c3 * av1;
            erp[mf][0][hw] += c0 * rv0 + c1 * rv1;
            erp[mf][1][hw] += c2 * rv0 + c3 * rv1;
        }
    }
#pragma unroll
    for (int mf = 0; mf < MFR; mf++)
#pragma unroll
        for (int hf = 0; hf < 2; hf++)
#pragma unroll
            for (int hh = 0; hh < HW; hh++) {
                float a = elp[mf][hf][hh], b = erp[mf][hf][hh];
                a += __shfl_xor_sync(0xffffffffu, a, 1);
                a += __shfl_xor_sync(0xffffffffu, a, 2);
                b += __shfl_xor_sync(0xffffffffu, b, 1);
                b += __shfl_xor_sync(0xffffffffu, b, 2);
                if ((lane & 3) == 0) {
                    int row = m0 + wr + mf * 16 + (lane >> 2) + hf * 8;
                    int hg = (n0 + warp_n * WN) / 32 + hh;
                    if (row < M) {
                        el[(size_t)row * H + hg] = a;
                        er[(size_t)row * H + hg] = b;
                    }
                }
            }
}

// ---------------------------------------------------------------------------
// Pull-style GAT aggregation over CSR.  Warp per (node, head), lane = dim.
// ---------------------------------------------------------------------------
__global__ void k_aggregate(const float* __restrict__ f,
                            const float* __restrict__ el,
                            const float* __restrict__ er,
                            const float* __restrict__ bias,
                            float* __restrict__ out,
                            int N, int H, int apply_elu) {
    int w = (blockIdx.x * blockDim.x + threadIdx.x) >> 5;
    int lane = threadIdx.x & 31;
    if (w >= N * H) return;
    int i = w / H, h = w % H;
    int s0 = g_rowptr[i], s1 = g_rowptr[i + 1];
    float er_i = er[i * H + h];
    float denom = 0.f, acc = 0.f;
    for (int j = s0; j < s1; j++) {
        int s = g_csrc[j];
        float e = el[s * H + h] + er_i;
        e = (e > 0.f) ? e : 0.2f * e;
        float a = __expf(e);
        denom += a;
        acc += a * f[(size_t)s * (H * DOUT) + h * DOUT + lane];
    }
    float o = (s1 > s0) ? (acc / denom) : 0.f;
    o += bias[h * DOUT + lane];
    if (apply_elu) o = (o > 0.f) ? o : (__expf(o) - 1.f);
    out[(size_t)i * (H * DOUT) + h * DOUT + lane] = o;
}

// ---------------------------------------------------------------------------
// Link predictor (unchanged)
// ---------------------------------------------------------------------------
__global__ void k_predictor(const float* __restrict__ h,
                            const int* __restrict__ ratio_ptr,
                            const float* __restrict__ P1, const float* __restrict__ pb1,
                            const float* __restrict__ P2, const float* __restrict__ pb2,
                            const float* __restrict__ P3, const float* __restrict__ pb3,
                            float* __restrict__ out, int N) {
    __shared__ float sP1[32 * 32], sP2[32 * 32], sP3[32], sb1[32], sb2[32];
    __shared__ float sb3;
    int t = threadIdx.x;
    for (int idx = t; idx < 1024; idx += blockDim.x) {
        sP1[idx] = P1[idx];
        sP2[idx] = P2[idx];
    }
    if (t < 32) { sP3[t] = P3[t]; sb1[t] = pb1[t]; sb2[t] = pb2[t]; }
    if (t == 0) sb3 = pb3[0];
    __syncthreads();

    int ratio = *ratio_ptr;
    int ne = N / (ratio + 2);
    int R = (1 + ratio) * ne;
    int lane = t & 31;
    int wpb = blockDim.x >> 5;
    for (int r = blockIdx.x * wpb + (t >> 5); r < R; r += gridDim.x * wpb) {
        int ia, ib, oi;
        if (r < ne) { ia = r; ib = r + ne; oi = r; }
        else {
            int j = r - ne;
            ia = j % ne; ib = 2 * ne + j; oi = ne + j;
        }
        float z = h[(size_t)ia * DOUT + lane] * h[(size_t)ib * DOUT + lane];

        float z1 = sb1[lane];
#pragma unroll
        for (int k = 0; k < 32; k++)
            z1 += __shfl_sync(0xffffffffu, z, k) * sP1[k * 32 + lane];
        z1 = fmaxf(z1, 0.f);

        float z2 = sb2[lane];
#pragma unroll
        for (int k = 0; k < 32; k++)
            z2 += __shfl_sync(0xffffffffu, z1, k) * sP2[k * 32 + lane];
        z2 = fmaxf(z2, 0.f);

        float v = z2 * sP3[lane];
#pragma unroll
        for (int off = 16; off; off >>= 1)
            v += __shfl_down_sync(0xffffffffu, v, off);
        if (lane == 0) out[oi] = v + sb3;
    }
}

// ---------------------------------------------------------------------------
// Launch.  Order chosen so ncu (-s 5) profiles aggregate layer 0.
// ---------------------------------------------------------------------------
extern "C" void kernel_launch(void* const* d_in, const int* in_sizes, int n_in,
                              void* d_out, int out_size) {
    const float* x    = (const float*)d_in[0];
    const int*   src  = (const int*)d_in[1];
    const int*   dst  = (const int*)d_in[2];
    const int*   nsr  = (const int*)d_in[3];
    const float* W0   = (const float*)d_in[4];
    const float* al0  = (const float*)d_in[5];
    const float* ar0  = (const float*)d_in[6];
    const float* b0   = (const float*)d_in[7];
    const float* W1   = (const float*)d_in[8];
    const float* al1  = (const float*)d_in[9];
    const float* ar1  = (const float*)d_in[10];
    const float* b1   = (const float*)d_in[11];
    const float* P1   = (const float*)d_in[12];
    const float* pb1  = (const float*)d_in[13];
    const float* P2   = (const float*)d_in[14];
    const float* pb2  = (const float*)d_in[15];
    const float* P3   = (const float*)d_in[16];
    const float* pb3  = (const float*)d_in[17];
    float* out = (float*)d_out;

    int N = in_sizes[0] / 128;
    int E = in_sizes[1];

    float *p_f0, *p_h0, *p_f1, *p_h1, *p_el0, *p_er0, *p_el1, *p_er1;
    cudaGetSymbolAddress((void**)&p_f0,  g_f0);
    cudaGetSymbolAddress((void**)&p_h0,  g_h0);
    cudaGetSymbolAddress((void**)&p_f1,  g_f1);
    cudaGetSymbolAddress((void**)&p_h1,  g_h1);
    cudaGetSymbolAddress((void**)&p_el0, g_el0);
    cudaGetSymbolAddress((void**)&p_er0, g_er0);
    cudaGetSymbolAddress((void**)&p_el1, g_el1);
    cudaGetSymbolAddress((void**)&p_er1, g_er1);

    int nbN = (N + 255) / 256;
    int nbE = (E + 255) / 256;

    // CSR build (by dst): launches 0..3
    k_zero_cnt<<<nbN, 256>>>(N);
    k_hist<<<nbE, 256>>>(dst, E);
    k_scan<<<1, 1024>>>(N);
    k_fill<<<nbE, 256>>>(src, dst, E);

    // layer 0: GEMM (tf32, fused scores) -> aggregate(+elu)   launches 4,5
    {
        dim3 grid(F0DIM / 128, (N + 127) / 128);
        k_gemm_tf32<128, 4, 2><<<grid, 256>>>(x, W0, p_f0, al0, ar0,
                                              p_el0, p_er0, N, F0DIM, 128, H0);
    }
    {
        long warps = (long)N * H0;
        int blocks = (int)((warps * 32 + 255) / 256);
        k_aggregate<<<blocks, 256>>>(p_f0, p_el0, p_er0, b0, p_h0, N, H0, 1);
    }

    // layer 1: GEMM (tf32, fused scores) -> aggregate          launches 6,7
    {
        dim3 grid(DOUT / 32, (N + 127) / 128);
        k_gemm_tf32<32, 8, 1><<<grid, 256>>>(p_h0, W1, p_f1, al1, ar1,
                                             p_el1, p_er1, N, DOUT, F0DIM, 1);
    }
    {
        int blocks = (N * 32 + 255) / 256;
        k_aggregate<<<blocks, 256>>>(p_f1, p_el1, p_er1, b1, p_h1, N, 1, 0);
    }

    // predictor                                                launch 8
    k_predictor<<<512, 256>>>(p_h1, nsr, P1, pb1, P2, pb2, P3, pb3, out, N);
}

// round 3
// speedup vs baseline: 1.4643x; 1.2692x over previous
#include <cuda_runtime.h>
#include <cuda_fp16.h>
#include <cstdint>
#include <cstddef>

// ---------------------------------------------------------------------------
// Problem constants (padded capacities for static scratch)
// ---------------------------------------------------------------------------
#define NMAX 50048
#define EMAX 1000064
#define H0 8
#define DOUT 32
#define F0DIM (H0*DOUT)     // 256

// ---------------------------------------------------------------------------
// Static device scratch
// ---------------------------------------------------------------------------
__device__ __half g_f16[(size_t)NMAX * F0DIM];   // layer-0 features (fp16)
__device__ float g_h0[(size_t)NMAX * F0DIM];     // layer-0 output (after elu)
__device__ float g_f1[(size_t)NMAX * DOUT];
__device__ float g_h1[(size_t)NMAX * DOUT];
__device__ float g_el0[(size_t)NMAX * H0];
__device__ float g_er0[(size_t)NMAX * H0];
__device__ float g_el1[NMAX];
__device__ float g_er1[NMAX];
__device__ float g_w0[(size_t)EMAX * H0];        // edge softmax numerators L0
__device__ float g_w1[EMAX];                     // edge softmax numerators L1
__device__ int   g_cnt[NMAX];
__device__ int   g_rowptr[NMAX + 1];
__device__ int   g_cursor[NMAX];
__device__ int   g_csrc[EMAX];
__device__ int   g_cdst[EMAX];

// ---------------------------------------------------------------------------
// CSR build
// ---------------------------------------------------------------------------
__global__ void k_zero_cnt(int N) {
    int i = blockIdx.x * blockDim.x + threadIdx.x;
    if (i < N) g_cnt[i] = 0;
}

__global__ void k_hist(const int* __restrict__ dst, int E) {
    int e = blockIdx.x * blockDim.x + threadIdx.x;
    if (e < E) atomicAdd(&g_cnt[dst[e]], 1);
}

__global__ void k_scan(int N) {
    __shared__ int s[1024];
    int t = threadIdx.x;
    int C = (N + 1023) / 1024;
    int beg = t * C;
    int end = beg + C; if (end > N) end = N;
    int sum = 0;
    for (int i = beg; i < end; i++) sum += g_cnt[i];
    s[t] = sum;
    __syncthreads();
    for (int off = 1; off < 1024; off <<= 1) {
        int u = (t >= off) ? s[t - off] : 0;
        __syncthreads();
        if (t >= off) s[t] += u;
        __syncthreads();
    }
    int pre = (t == 0) ? 0 : s[t - 1];
    for (int i = beg; i < end; i++) {
        int c = g_cnt[i];
        g_rowptr[i] = pre;
        g_cursor[i] = pre;
        pre += c;
    }
    if (t == 1023) g_rowptr[N] = s[1023];
}

__global__ void k_fill(const int* __restrict__ src, const int* __restrict__ dst, int E) {
    int e = blockIdx.x * blockDim.x + threadIdx.x;
    if (e < E) {
        int d = dst[e];
        int p = atomicAdd(&g_cursor[d], 1);
        g_csrc[p] = src[e];
        g_cdst[p] = d;
    }
}

// ---------------------------------------------------------------------------
// Edge softmax numerators, lane-parallel over (csr_pos, head)
// ---------------------------------------------------------------------------
template<int H>
__global__ void k_weights(const float* __restrict__ el,
                          const float* __restrict__ er,
                          float* __restrict__ w, int E) {
    int idx = blockIdx.x * blockDim.x + threadIdx.x;
    if (idx >= E * H) return;
    int j = (H == 1) ? idx : (idx / H);
    int h = (H == 1) ? 0 : (idx & (H - 1));
    int s = g_csrc[j], d = g_cdst[j];
    float e = el[s * H + h] + er[d * H + h];
    e = (e > 0.f) ? e : 0.2f * e;
    w[idx] = __expf(e);
}

// ---------------------------------------------------------------------------
// TF32 tensor-core GEMM with fused attention-score epilogue.
// ---------------------------------------------------------------------------
__device__ __forceinline__ uint32_t f2tf32(float v) {
    uint32_t u;
    asm("cvt.rna.tf32.f32 %0, %1;" : "=r"(u) : "f"(v));
    return u;
}

template<int BN, int WMI, int WNI, bool HALF_OUT>
__global__ __launch_bounds__(256) void k_gemm_tf32(
    const float* __restrict__ A, const float* __restrict__ B,
    void* __restrict__ Cv,
    const float* __restrict__ al, const float* __restrict__ ar,
    float* __restrict__ el, float* __restrict__ er,
    int M, int N, int K, int H)
{
    constexpr int BM = 128;
    constexpr int BK = 32;
    constexpr int WM = BM / WMI;
    constexpr int WN = BN / WNI;
    constexpr int MFR = WM / 16;
    constexpr int NFR = WN / 8;
    constexpr int HW  = (WN + 31) / 32;
    constexpr int AS_STRIDE = 36;
    constexpr int BS_STRIDE = BN + 8;

    __shared__ uint32_t As[BM * AS_STRIDE];
    __shared__ uint32_t Bs[BK * BS_STRIDE];

    int tid = threadIdx.x;
    int lane = tid & 31;
    int w = tid >> 5;
    int warp_m = w % WMI;
    int warp_n = w / WMI;
    int m0 = blockIdx.y * BM;
    int n0 = blockIdx.x * BN;
    int wr = warp_m * WM;

    float c[MFR][NFR][4];
#pragma unroll
    for (int i = 0; i < MFR; i++)
#pragma unroll
        for (int j = 0; j < NFR; j++)
#pragma unroll
            for (int q = 0; q < 4; q++) c[i][j][q] = 0.f;

    for (int k0 = 0; k0 < K; k0 += BK) {
#pragma unroll
        for (int q = 0; q < (BM * BK / 4) / 256; q++) {
            int idx = tid + q * 256;
            int row = idx >> 3;
            int c4  = idx & 7;
            uint4 u = make_uint4(0u, 0u, 0u, 0u);
            int grow = m0 + row;
            if (grow < M) {
                float4 v = *(const float4*)(A + (size_t)grow * K + k0 + c4 * 4);
                u.x = f2tf32(v.x); u.y = f2tf32(v.y);
                u.z = f2tf32(v.z); u.w = f2tf32(v.w);
            }
            *(uint4*)&As[row * AS_STRIDE + c4 * 4] = u;
        }
#pragma unroll
        for (int q = 0; q < (BK * BN / 4) / 256; q++) {
            int idx = tid + q * 256;
            int row = idx / (BN / 4);
            int c4  = idx % (BN / 4);
            float4 v = *(const float4*)(B + (size_t)(k0 + row) * N + n0 + c4 * 4);
            uint4 u;
            u.x = f2tf32(v.x); u.y = f2tf32(v.y);
            u.z = f2tf32(v.z); u.w = f2tf32(v.w);
            *(uint4*)&Bs[row * BS_STRIDE + c4 * 4] = u;
        }
        __syncthreads();

#pragma unroll
        for (int kk = 0; kk < BK; kk += 8) {
            uint32_t af[MFR][4];
#pragma unroll
            for (int mf = 0; mf < MFR; mf++) {
                int r = wr + mf * 16 + (lane >> 2);
                int kc = kk + (lane & 3);
                af[mf][0] = As[r * AS_STRIDE + kc];
                af[mf][1] = As[(r + 8) * AS_STRIDE + kc];
                af[mf][2] = As[r * AS_STRIDE + kc + 4];
                af[mf][3] = As[(r + 8) * AS_STRIDE + kc + 4];
            }
            uint32_t bf[NFR][2];
#pragma unroll
            for (int nf = 0; nf < NFR; nf++) {
                int n = warp_n * WN + nf * 8 + (lane >> 2);
                int kc = kk + (lane & 3);
                bf[nf][0] = Bs[kc * BS_STRIDE + n];
                bf[nf][1] = Bs[(kc + 4) * BS_STRIDE + n];
            }
#pragma unroll
            for (int mf = 0; mf < MFR; mf++)
#pragma unroll
                for (int nf = 0; nf < NFR; nf++) {
                    asm volatile(
                        "mma.sync.aligned.m16n8k8.row.col.f32.tf32.tf32.f32 "
                        "{%0,%1,%2,%3}, {%4,%5,%6,%7}, {%8,%9}, {%0,%1,%2,%3};\n"
                        : "+f"(c[mf][nf][0]), "+f"(c[mf][nf][1]),
                          "+f"(c[mf][nf][2]), "+f"(c[mf][nf][3])
                        : "r"(af[mf][0]), "r"(af[mf][1]), "r"(af[mf][2]), "r"(af[mf][3]),
                          "r"(bf[nf][0]), "r"(bf[nf][1]));
                }
        }
        __syncthreads();
    }

    // --- epilogue: store C (fp16 or fp32), accumulate per-head score dots ---
    float elp[MFR][2][HW], erp[MFR][2][HW];
#pragma unroll
    for (int mf = 0; mf < MFR; mf++)
#pragma unroll
        for (int hf = 0; hf < 2; hf++)
#pragma unroll
            for (int hh = 0; hh < HW; hh++) { elp[mf][hf][hh] = 0.f; erp[mf][hf][hh] = 0.f; }

#pragma unroll
    for (int nf = 0; nf < NFR; nf++) {
        int colb = warp_n * WN + nf * 8;
        int hw = (nf * 8) >> 5;
        int hg = (n0 + colb) >> 5;
        int ch = (colb & 31) + 2 * (lane & 3);
        float av0 = al[hg * 32 + ch], av1 = al[hg * 32 + ch + 1];
        float rv0 = ar[hg * 32 + ch], rv1 = ar[hg * 32 + ch + 1];
        int gcol = n0 + colb + 2 * (lane & 3);
#pragma unroll
        for (int mf = 0; mf < MFR; mf++) {
            int r0 = m0 + wr + mf * 16 + (lane >> 2);
            int r1 = r0 + 8;
            float c0 = c[mf][nf][0], c1 = c[mf][nf][1];
            float c2 = c[mf][nf][2], c3 = c[mf][nf][3];
            if (HALF_OUT) {
                __half* C = (__half*)Cv;
                if (r0 < M) *(__half2*)(C + (size_t)r0 * N + gcol) = __floats2half2_rn(c0, c1);
                if (r1 < M) *(__half2*)(C + (size_t)r1 * N + gcol) = __floats2half2_rn(c2, c3);
            } else {
                float* C = (float*)Cv;
                if (r0 < M) *(float2*)(C + (size_t)r0 * N + gcol) = make_float2(c0, c1);
                if (r1 < M) *(float2*)(C + (size_t)r1 * N + gcol) = make_float2(c2, c3);
            }
            elp[mf][0][hw] += c0 * av0 + c1 * av1;
            elp[mf][1][hw] += c2 * av0 + c3 * av1;
            erp[mf][0][hw] += c0 * rv0 + c1 * rv1;
            erp[mf][1][hw] += c2 * rv0 + c3 * rv1;
        }
    }
#pragma unroll
    for (int mf = 0; mf < MFR; mf++)
#pragma unroll
        for (int hf = 0; hf < 2; hf++)
#pragma unroll
            for (int hh = 0; hh < HW; hh++) {
                float a = elp[mf][hf][hh], b = erp[mf][hf][hh];
                a += __shfl_xor_sync(0xffffffffu, a, 1);
                a += __shfl_xor_sync(0xffffffffu, a, 2);
                b += __shfl_xor_sync(0xffffffffu, b, 1);
                b += __shfl_xor_sync(0xffffffffu, b, 2);
                if ((lane & 3) == 0) {
                    int row = m0 + wr + mf * 16 + (lane >> 2) + hf * 8;
                    int hg = (n0 + warp_n * WN) / 32 + hh;
                    if (row < M) {
                        el[(size_t)row * H + hg] = a;
                        er[(size_t)row * H + hg] = b;
                    }
                }
            }
}

// ---------------------------------------------------------------------------
// Layer-0 aggregation: block(128) per node; warp = head-pair (2w, 2w+1);
// lanes 0-15 -> head 2w, lanes 16-31 -> head 2w+1; each lane owns 2 dims
// via half2. Edge list staged in smem; 2-way unrolled for MLP.
// ---------------------------------------------------------------------------
__global__ __launch_bounds__(128) void k_agg0(const __half* __restrict__ f16,
                                              const float* __restrict__ wgt,
                                              const float* __restrict__ bias,
                                              float* __restrict__ out, int N) {
    __shared__ int se[128];
    int i = blockIdx.x;
    if (i >= N) return;
    int t = threadIdx.x, lane = t & 31, wid = t >> 5;
    int s0 = g_rowptr[i], s1 = g_rowptr[i + 1];
    int hidx = wid * 2 + (lane >> 4);             // this half-warp's head
    float2 accA = make_float2(0.f, 0.f), accB = make_float2(0.f, 0.f);
    float denA = 0.f, denB = 0.f;

    for (int base = s0; base < s1; base += 128) {
        int cnt = min(128, s1 - base);
        __syncthreads();
        if (t < cnt) se[t] = g_csrc[base + t];
        __syncthreads();
        int j = 0;
        for (; j + 1 < cnt; j += 2) {
            int sA = se[j], sB = se[j + 1];
            float aA = wgt[(size_t)(base + j) * H0 + hidx];
            float aB = wgt[(size_t)(base + j + 1) * H0 + hidx];
            __half2 hA = *((const __half2*)(f16 + (size_t)sA * F0DIM + wid * 64) + lane);
            __half2 hB = *((const __half2*)(f16 + (size_t)sB * F0DIM + wid * 64) + lane);
            float2 vA = __half22float2(hA);
            float2 vB = __half22float2(hB);
            accA.x += aA * vA.x; accA.y += aA * vA.y; denA += aA;
            accB.x += aB * vB.x; accB.y += aB * vB.y; denB += aB;
        }
        if (j < cnt) {
            int sA = se[j];
            float aA = wgt[(size_t)(base + j) * H0 + hidx];
            __half2 hA = *((const __half2*)(f16 + (size_t)sA * F0DIM + wid * 64) + lane);
            float2 vA = __half22float2(hA);
            accA.x += aA * vA.x; accA.y += aA * vA.y; denA += aA;
        }
    }
    float den = denA + denB;
    float inv = (s1 > s0) ? (1.f / den) : 0.f;
    int off = wid * 64 + lane * 2;
    float o0 = (accA.x + accB.x) * inv + bias[off];
    float o1 = (accA.y + accB.y) * inv + bias[off + 1];
    o0 = (o0 > 0.f) ? o0 : (__expf(o0) - 1.f);
    o1 = (o1 > 0.f) ? o1 : (__expf(o1) - 1.f);
    *(float2*)(out + (size_t)i * F0DIM + off) = make_float2(o0, o1);
}

// ---------------------------------------------------------------------------
// Layer-1 aggregation: warp per node, lane = dim, weights precomputed.
// ---------------------------------------------------------------------------
__global__ void k_agg1(const float* __restrict__ f,
                       const float* __restrict__ wgt,
                       const float* __restrict__ bias,
                       float* __restrict__ out, int N) {
    int w = (blockIdx.x * blockDim.x + threadIdx.x) >> 5;
    int lane = threadIdx.x & 31;
    if (w >= N) return;
    int s0 = g_rowptr[w], s1 = g_rowptr[w + 1];
    float accA = 0.f, accB = 0.f, denA = 0.f, denB = 0.f;
    int j = s0;
    for (; j + 1 < s1; j += 2) {
        int sA = g_csrc[j], sB = g_csrc[j + 1];
        float aA = wgt[j], aB = wgt[j + 1];
        accA += aA * f[(size_t)sA * DOUT + lane];
        accB += aB * f[(size_t)sB * DOUT + lane];
        denA += aA; denB += aB;
    }
    if (j < s1) {
        int sA = g_csrc[j];
        float aA = wgt[j];
        accA += aA * f[(size_t)sA * DOUT + lane];
        denA += aA;
    }
    float den = denA + denB;
    float o = (s1 > s0) ? ((accA + accB) / den) : 0.f;
    out[(size_t)w * DOUT + lane] = o + bias[lane];
}

// ---------------------------------------------------------------------------
// Link predictor
// ---------------------------------------------------------------------------
__global__ void k_predictor(const float* __restrict__ h,
                            const int* __restrict__ ratio_ptr,
                            const float* __restrict__ P1, const float* __restrict__ pb1,
                            const float* __restrict__ P2, const float* __restrict__ pb2,
                            const float* __restrict__ P3, const float* __restrict__ pb3,
                            float* __restrict__ out, int N) {
    __shared__ float sP1[32 * 32], sP2[32 * 32], sP3[32], sb1[32], sb2[32];
    __shared__ float sb3;
    int t = threadIdx.x;
    for (int idx = t; idx < 1024; idx += blockDim.x) {
        sP1[idx] = P1[idx];
        sP2[idx] = P2[idx];
    }
    if (t < 32) { sP3[t] = P3[t]; sb1[t] = pb1[t]; sb2[t] = pb2[t]; }
    if (t == 0) sb3 = pb3[0];
    __syncthreads();

    int ratio = *ratio_ptr;
    int ne = N / (ratio + 2);
    int R = (1 + ratio) * ne;
    int lane = t & 31;
    int wpb = blockDim.x >> 5;
    for (int r = blockIdx.x * wpb + (t >> 5); r < R; r += gridDim.x * wpb) {
        int ia, ib, oi;
        if (r < ne) { ia = r; ib = r + ne; oi = r; }
        else {
            int j = r - ne;
            ia = j % ne; ib = 2 * ne + j; oi = ne + j;
        }
        float z = h[(size_t)ia * DOUT + lane] * h[(size_t)ib * DOUT + lane];

        float z1 = sb1[lane];
#pragma unroll
        for (int k = 0; k < 32; k++)
            z1 += __shfl_sync(0xffffffffu, z, k) * sP1[k * 32 + lane];
        z1 = fmaxf(z1, 0.f);

        float z2 = sb2[lane];
#pragma unroll
        for (int k = 0; k < 32; k++)
            z2 += __shfl_sync(0xffffffffu, z1, k) * sP2[k * 32 + lane];
        z2 = fmaxf(z2, 0.f);

        float v = z2 * sP3[lane];
#pragma unroll
        for (int off = 16; off; off >>= 1)
            v += __shfl_down_sync(0xffffffffu, v, off);
        if (lane == 0) out[oi] = v + sb3;
    }
}

// ---------------------------------------------------------------------------
// Launch.  gemm0 placed at my-launch-index 3 (ncu profiles that slot).
// ---------------------------------------------------------------------------
extern "C" void kernel_launch(void* const* d_in, const int* in_sizes, int n_in,
                              void* d_out, int out_size) {
    const float* x    = (const float*)d_in[0];
    const int*   src  = (const int*)d_in[1];
    const int*   dst  = (const int*)d_in[2];
    const int*   nsr  = (const int*)d_in[3];
    const float* W0   = (const float*)d_in[4];
    const float* al0  = (const float*)d_in[5];
    const float* ar0  = (const float*)d_in[6];
    const float* b0   = (const float*)d_in[7];
    const float* W1   = (const float*)d_in[8];
    const float* al1  = (const float*)d_in[9];
    const float* ar1  = (const float*)d_in[10];
    const float* b1   = (const float*)d_in[11];
    const float* P1   = (const float*)d_in[12];
    const float* pb1  = (const float*)d_in[13];
    const float* P2   = (const float*)d_in[14];
    const float* pb2  = (const float*)d_in[15];
    const float* P3   = (const float*)d_in[16];
    const float* pb3  = (const float*)d_in[17];
    float* out = (float*)d_out;

    int N = in_sizes[0] / 128;
    int E = in_sizes[1];

    __half* p_f16; float *p_h0, *p_f1, *p_h1, *p_el0, *p_er0, *p_el1, *p_er1, *p_w0, *p_w1;
    cudaGetSymbolAddress((void**)&p_f16, g_f16);
    cudaGetSymbolAddress((void**)&p_h0,  g_h0);
    cudaGetSymbolAddress((void**)&p_f1,  g_f1);
    cudaGetSymbolAddress((void**)&p_h1,  g_h1);
    cudaGetSymbolAddress((void**)&p_el0, g_el0);
    cudaGetSymbolAddress((void**)&p_er0, g_er0);
    cudaGetSymbolAddress((void**)&p_el1, g_el1);
    cudaGetSymbolAddress((void**)&p_er1, g_er1);
    cudaGetSymbolAddress((void**)&p_w0,  g_w0);
    cudaGetSymbolAddress((void**)&p_w1,  g_w1);

    int nbN = (N + 255) / 256;
    int nbE = (E + 255) / 256;

    // 0..2: CSR histogram + scan
    k_zero_cnt<<<nbN, 256>>>(N);
    k_hist<<<nbE, 256>>>(dst, E);
    k_scan<<<1, 1024>>>(N);

    // 3: layer-0 GEMM (profiled slot)
    {
        dim3 grid(F0DIM / 128, (N + 127) / 128);
        k_gemm_tf32<128, 4, 2, true><<<grid, 256>>>(x, W0, p_f16, al0, ar0,
                                                    p_el0, p_er0, N, F0DIM, 128, H0);
    }

    // 4: CSR fill
    k_fill<<<nbE, 256>>>(src, dst, E);

    // 5: layer-0 edge weights; 6: aggregation
    k_weights<H0><<<(E * H0 + 255) / 256, 256>>>(p_el0, p_er0, p_w0, E);
    k_agg0<<<N, 128>>>(p_f16, p_w0, b0, p_h0, N);

    // 7: layer-1 GEMM; 8: weights; 9: aggregation
    {
        dim3 grid(DOUT / 32, (N + 127) / 128);
        k_gemm_tf32<32, 8, 1, false><<<grid, 256>>>(p_h0, W1, p_f1, al1, ar1,
                                                    p_el1, p_er1, N, DOUT, F0DIM, 1);
    }
    k_weights<1><<<(E + 255) / 256, 256>>>(p_el1, p_er1, p_w1, E);
    k_agg1<<<(N * 32 + 255) / 256, 256>>>(p_f1, p_w1, b1, p_h1, N);

    // 10: predictor
    k_predictor<<<512, 256>>>(p_h1, nsr, P1, pb1, P2, pb2, P3, pb3, out, N);
}

// round 5
// speedup vs baseline: 1.5677x; 1.0706x over previous
#include <cuda_runtime.h>
#include <cuda_fp16.h>
#include <cstdint>
#include <cstddef>

// ---------------------------------------------------------------------------
// Problem constants (padded capacities for static scratch)
// ---------------------------------------------------------------------------
#define NMAX 50048
#define EMAX 1000064
#define H0 8
#define DOUT 32
#define F0DIM (H0*DOUT)     // 256

// ---------------------------------------------------------------------------
// Static device scratch
// ---------------------------------------------------------------------------
__device__ __half g_f16[(size_t)NMAX * F0DIM];   // layer-0 features (fp16)
__device__ float g_h0[(size_t)NMAX * F0DIM];     // layer-0 output (after elu)
__device__ float g_f1[(size_t)NMAX * DOUT];
__device__ float g_h1[(size_t)NMAX * DOUT];
__device__ float g_el0[(size_t)NMAX * H0];
__device__ float g_er0[(size_t)NMAX * H0];
__device__ float g_el1[NMAX];
__device__ float g_er1[NMAX];
__device__ int   g_cnt[NMAX];
__device__ int   g_rowptr[NMAX + 1];
__device__ int   g_cursor[NMAX];
__device__ int   g_csrc[EMAX];

// ---------------------------------------------------------------------------
// CSR build
// ---------------------------------------------------------------------------
__global__ void k_hist(const int* __restrict__ dst, int E) {
    int e = blockIdx.x * blockDim.x + threadIdx.x;
    if (e < E) atomicAdd(&g_cnt[dst[e]], 1);
}

__global__ void k_scan(int N) {
    __shared__ int s[1024];
    int t = threadIdx.x;
    int C = (N + 1023) / 1024;
    int beg = t * C;
    int end = beg + C; if (end > N) end = N;
    int sum = 0;
    for (int i = beg; i < end; i++) sum += g_cnt[i];
    s[t] = sum;
    __syncthreads();
    for (int off = 1; off < 1024; off <<= 1) {
        int u = (t >= off) ? s[t - off] : 0;
        __syncthreads();
        if (t >= off) s[t] += u;
        __syncthreads();
    }
    int pre = (t == 0) ? 0 : s[t - 1];
    for (int i = beg; i < end; i++) {
        int c = g_cnt[i];
        g_rowptr[i] = pre;
        g_cursor[i] = pre;
        pre += c;
    }
    if (t == 1023) g_rowptr[N] = s[1023];
}

__global__ void k_fill(const int* __restrict__ src, const int* __restrict__ dst, int E) {
    int e = blockIdx.x * blockDim.x + threadIdx.x;
    if (e < E) {
        int p = atomicAdd(&g_cursor[dst[e]], 1);
        g_csrc[p] = src[e];
    }
}

// ---------------------------------------------------------------------------
// TF32 tensor-core GEMM with fused attention-score epilogue.
// ---------------------------------------------------------------------------
__device__ __forceinline__ uint32_t f2tf32(float v) {
    uint32_t u;
    asm("cvt.rna.tf32.f32 %0, %1;" : "=r"(u) : "f"(v));
    return u;
}

template<int BN, int WMI, int WNI, bool HALF_OUT>
__global__ __launch_bounds__(256) void k_gemm_tf32(
    const float* __restrict__ A, const float* __restrict__ B,
    void* __restrict__ Cv,
    const float* __restrict__ al, const float* __restrict__ ar,
    float* __restrict__ el, float* __restrict__ er,
    int M, int N, int K, int H)
{
    constexpr int BM = 128;
    constexpr int BK = 32;
    constexpr int WM = BM / WMI;
    constexpr int WN = BN / WNI;
    constexpr int MFR = WM / 16;
    constexpr int NFR = WN / 8;
    constexpr int HW  = (WN + 31) / 32;
    constexpr int AS_STRIDE = 36;
    constexpr int BS_STRIDE = BN + 8;

    __shared__ uint32_t As[BM * AS_STRIDE];
    __shared__ uint32_t Bs[BK * BS_STRIDE];

    int tid = threadIdx.x;
    int lane = tid & 31;
    int w = tid >> 5;
    int warp_m = w % WMI;
    int warp_n = w / WMI;
    int m0 = blockIdx.y * BM;
    int n0 = blockIdx.x * BN;
    int wr = warp_m * WM;

    float c[MFR][NFR][4];
#pragma unroll
    for (int i = 0; i < MFR; i++)
#pragma unroll
        for (int j = 0; j < NFR; j++)
#pragma unroll
            for (int q = 0; q < 4; q++) c[i][j][q] = 0.f;

    for (int k0 = 0; k0 < K; k0 += BK) {
#pragma unroll
        for (int q = 0; q < (BM * BK / 4) / 256; q++) {
            int idx = tid + q * 256;
            int row = idx >> 3;
            int c4  = idx & 7;
            uint4 u = make_uint4(0u, 0u, 0u, 0u);
            int grow = m0 + row;
            if (grow < M) {
                float4 v = *(const float4*)(A + (size_t)grow * K + k0 + c4 * 4);
                u.x = f2tf32(v.x); u.y = f2tf32(v.y);
                u.z = f2tf32(v.z); u.w = f2tf32(v.w);
            }
            *(uint4*)&As[row * AS_STRIDE + c4 * 4] = u;
        }
#pragma unroll
        for (int q = 0; q < (BK * BN / 4) / 256; q++) {
            int idx = tid + q * 256;
            int row = idx / (BN / 4);
            int c4  = idx % (BN / 4);
            float4 v = *(const float4*)(B + (size_t)(k0 + row) * N + n0 + c4 * 4);
            uint4 u;
            u.x = f2tf32(v.x); u.y = f2tf32(v.y);
            u.z = f2tf32(v.z); u.w = f2tf32(v.w);
            *(uint4*)&Bs[row * BS_STRIDE + c4 * 4] = u;
        }
        __syncthreads();

#pragma unroll
        for (int kk = 0; kk < BK; kk += 8) {
            uint32_t af[MFR][4];
#pragma unroll
            for (int mf = 0; mf < MFR; mf++) {
                int r = wr + mf * 16 + (lane >> 2);
                int kc = kk + (lane & 3);
                af[mf][0] = As[r * AS_STRIDE + kc];
                af[mf][1] = As[(r + 8) * AS_STRIDE + kc];
                af[mf][2] = As[r * AS_STRIDE + kc + 4];
                af[mf][3] = As[(r + 8) * AS_STRIDE + kc + 4];
            }
            uint32_t bf[NFR][2];
#pragma unroll
            for (int nf = 0; nf < NFR; nf++) {
                int n = warp_n * WN + nf * 8 + (lane >> 2);
                int kc = kk + (lane & 3);
                bf[nf][0] = Bs[kc * BS_STRIDE + n];
                bf[nf][1] = Bs[(kc + 4) * BS_STRIDE + n];
            }
#pragma unroll
            for (int mf = 0; mf < MFR; mf++)
#pragma unroll
                for (int nf = 0; nf < NFR; nf++) {
                    asm volatile(
                        "mma.sync.aligned.m16n8k8.row.col.f32.tf32.tf32.f32 "
                        "{%0,%1,%2,%3}, {%4,%5,%6,%7}, {%8,%9}, {%0,%1,%2,%3};\n"
                        : "+f"(c[mf][nf][0]), "+f"(c[mf][nf][1]),
                          "+f"(c[mf][nf][2]), "+f"(c[mf][nf][3])
                        : "r"(af[mf][0]), "r"(af[mf][1]), "r"(af[mf][2]), "r"(af[mf][3]),
                          "r"(bf[nf][0]), "r"(bf[nf][1]));
                }
        }
        __syncthreads();
    }

    float elp[MFR][2][HW], erp[MFR][2][HW];
#pragma unroll
    for (int mf = 0; mf < MFR; mf++)
#pragma unroll
        for (int hf = 0; hf < 2; hf++)
#pragma unroll
            for (int hh = 0; hh < HW; hh++) { elp[mf][hf][hh] = 0.f; erp[mf][hf][hh] = 0.f; }

#pragma unroll
    for (int nf = 0; nf < NFR; nf++) {
        int colb = warp_n * WN + nf * 8;
        int hw = (nf * 8) >> 5;
        int hg = (n0 + colb) >> 5;
        int ch = (colb & 31) + 2 * (lane & 3);
        float av0 = al[hg * 32 + ch], av1 = al[hg * 32 + ch + 1];
        float rv0 = ar[hg * 32 + ch], rv1 = ar[hg * 32 + ch + 1];
        int gcol = n0 + colb + 2 * (lane & 3);
#pragma unroll
        for (int mf = 0; mf < MFR; mf++) {
            int r0 = m0 + wr + mf * 16 + (lane >> 2);
            int r1 = r0 + 8;
            float c0 = c[mf][nf][0], c1 = c[mf][nf][1];
            float c2 = c[mf][nf][2], c3 = c[mf][nf][3];
            if (HALF_OUT) {
                __half* C = (__half*)Cv;
                if (r0 < M) *(__half2*)(C + (size_t)r0 * N + gcol) = __floats2half2_rn(c0, c1);
                if (r1 < M) *(__half2*)(C + (size_t)r1 * N + gcol) = __floats2half2_rn(c2, c3);
            } else {
                float* C = (float*)Cv;
                if (r0 < M) *(float2*)(C + (size_t)r0 * N + gcol) = make_float2(c0, c1);
                if (r1 < M) *(float2*)(C + (size_t)r1 * N + gcol) = make_float2(c2, c3);
            }
            elp[mf][0][hw] += c0 * av0 + c1 * av1;
            elp[mf][1][hw] += c2 * av0 + c3 * av1;
            erp[mf][0][hw] += c0 * rv0 + c1 * rv1;
            erp[mf][1][hw] += c2 * rv0 + c3 * rv1;
        }
    }
#pragma unroll
    for (int mf = 0; mf < MFR; mf++)
#pragma unroll
        for (int hf = 0; hf < 2; hf++)
#pragma unroll
            for (int hh = 0; hh < HW; hh++) {
                float a = elp[mf][hf][hh], b = erp[mf][hf][hh];
                a += __shfl_xor_sync(0xffffffffu, a, 1);
                a += __shfl_xor_sync(0xffffffffu, a, 2);
                b += __shfl_xor_sync(0xffffffffu, b, 1);
                b += __shfl_xor_sync(0xffffffffu, b, 2);
                if ((lane & 3) == 0) {
                    int row = m0 + wr + mf * 16 + (lane >> 2) + hf * 8;
                    int hg = (n0 + warp_n * WN) / 32 + hh;
                    if (row < M) {
                        el[(size_t)row * H + hg] = a;
                        er[(size_t)row * H + hg] = b;
                    }
                }
            }
}

// ---------------------------------------------------------------------------
// Layer-0 aggregation with FUSED edge weights.
// Block(128) per node i. er_i is loop-invariant (dst == i). Per 128-edge
// tile: stage src ids, cooperatively compute exp(lrelu(el+er)) for all
// (edge, head) into smem, then warp = head-pair weighted-average of fp16 rows.
// ---------------------------------------------------------------------------
__global__ __launch_bounds__(128) void k_agg0(const __half* __restrict__ f16,
                                              const float* __restrict__ el,
                                              const float* __restrict__ er,
                                              const float* __restrict__ bias,
                                              float* __restrict__ out, int N) {
    __shared__ int   se[128];
    __shared__ float sw[128 * H0];
    __shared__ float ser[H0];
    int i = blockIdx.x;
    if (i >= N) return;
    int t = threadIdx.x, lane = t & 31, wid = t >> 5;
    if (t < H0) ser[t] = er[i * H0 + t];
    int s0 = g_rowptr[i], s1 = g_rowptr[i + 1];
    int hidx = wid * 2 + (lane >> 4);
    float2 accA = make_float2(0.f, 0.f), accB = make_float2(0.f, 0.f);
    float denA = 0.f, denB = 0.f;

    for (int base = s0; base < s1; base += 128) {
        int cnt = min(128, s1 - base);
        __syncthreads();                      // prev-iter reads done; ser visible
        if (t < cnt) se[t] = g_csrc[base + t];
        __syncthreads();
        for (int idx = t; idx < cnt * H0; idx += 128) {
            int j = idx >> 3, h = idx & 7;
            float e = el[se[j] * H0 + h] + ser[h];
            e = (e > 0.f) ? e : 0.2f * e;
            sw[idx] = __expf(e);
        }
        __syncthreads();
        int j = 0;
        for (; j + 1 < cnt; j += 2) {
            int sA = se[j], sB = se[j + 1];
            float aA = sw[j * H0 + hidx];
            float aB = sw[(j + 1) * H0 + hidx];
            __half2 hA = *((const __half2*)(f16 + (size_t)sA * F0DIM + wid * 64) + lane);
            __half2 hB = *((const __half2*)(f16 + (size_t)sB * F0DIM + wid * 64) + lane);
            float2 vA = __half22float2(hA);
            float2 vB = __half22float2(hB);
            accA.x += aA * vA.x; accA.y += aA * vA.y; denA += aA;
            accB.x += aB * vB.x; accB.y += aB * vB.y; denB += aB;
        }
        if (j < cnt) {
            int sA = se[j];
            float aA = sw[j * H0 + hidx];
            __half2 hA = *((const __half2*)(f16 + (size_t)sA * F0DIM + wid * 64) + lane);
            float2 vA = __half22float2(hA);
            accA.x += aA * vA.x; accA.y += aA * vA.y; denA += aA;
        }
    }
    float den = denA + denB;
    float inv = (s1 > s0) ? (1.f / den) : 0.f;
    int off = wid * 64 + lane * 2;
    float o0 = (accA.x + accB.x) * inv + bias[off];
    float o1 = (accA.y + accB.y) * inv + bias[off + 1];
    o0 = (o0 > 0.f) ? o0 : (__expf(o0) - 1.f);
    o1 = (o1 > 0.f) ? o1 : (__expf(o1) - 1.f);
    *(float2*)(out + (size_t)i * F0DIM + off) = make_float2(o0, o1);
}

// ---------------------------------------------------------------------------
// Layer-1 aggregation with FUSED edge weights. Warp per node, lane = dim.
// ---------------------------------------------------------------------------
__global__ void k_agg1(const float* __restrict__ f,
                       const float* __restrict__ el,
                       const float* __restrict__ er,
                       const float* __restrict__ bias,
                       float* __restrict__ out, int N) {
    int w = (blockIdx.x * blockDim.x + threadIdx.x) >> 5;
    int lane = threadIdx.x & 31;
    if (w >= N) return;
    int s0 = g_rowptr[w], s1 = g_rowptr[w + 1];
    float er_i = er[w];
    float accA = 0.f, accB = 0.f, denA = 0.f, denB = 0.f;
    int j = s0;
    for (; j + 1 < s1; j += 2) {
        int sA = g_csrc[j], sB = g_csrc[j + 1];
        float eA = el[sA] + er_i;
        float eB = el[sB] + er_i;
        eA = (eA > 0.f) ? eA : 0.2f * eA;
        eB = (eB > 0.f) ? eB : 0.2f * eB;
        float aA = __expf(eA), aB = __expf(eB);
        accA += aA * f[(size_t)sA * DOUT + lane];
        accB += aB * f[(size_t)sB * DOUT + lane];
        denA += aA; denB += aB;
    }
    if (j < s1) {
        int sA = g_csrc[j];
        float eA = el[sA] + er_i;
        eA = (eA > 0.f) ? eA : 0.2f * eA;
        float aA = __expf(eA);
        accA += aA * f[(size_t)sA * DOUT + lane];
        denA += aA;
    }
    float den = denA + denB;
    float o = (s1 > s0) ? ((accA + accB) / den) : 0.f;
    out[(size_t)w * DOUT + lane] = o + bias[lane];
}

// ---------------------------------------------------------------------------
// Link predictor
// ---------------------------------------------------------------------------
__global__ void k_predictor(const float* __restrict__ h,
                            const int* __restrict__ ratio_ptr,
                            const float* __restrict__ P1, const float* __restrict__ pb1,
                            const float* __restrict__ P2, const float* __restrict__ pb2,
                            const float* __restrict__ P3, const float* __restrict__ pb3,
                            float* __restrict__ out, int N) {
    __shared__ float sP1[32 * 32], sP2[32 * 32], sP3[32], sb1[32], sb2[32];
    __shared__ float sb3;
    int t = threadIdx.x;
    for (int idx = t; idx < 1024; idx += blockDim.x) {
        sP1[idx] = P1[idx];
        sP2[idx] = P2[idx];
    }
    if (t < 32) { sP3[t] = P3[t]; sb1[t] = pb1[t]; sb2[t] = pb2[t]; }
    if (t == 0) sb3 = pb3[0];
    __syncthreads();

    int ratio = *ratio_ptr;
    int ne = N / (ratio + 2);
    int R = (1 + ratio) * ne;
    int lane = t & 31;
    int wpb = blockDim.x >> 5;
    for (int r = blockIdx.x * wpb + (t >> 5); r < R; r += gridDim.x * wpb) {
        int ia, ib, oi;
        if (r < ne) { ia = r; ib = r + ne; oi = r; }
        else {
            int j = r - ne;
            ia = j % ne; ib = 2 * ne + j; oi = ne + j;
        }
        float z = h[(size_t)ia * DOUT + lane] * h[(size_t)ib * DOUT + lane];

        float z1 = sb1[lane];
#pragma unroll
        for (int k = 0; k < 32; k++)
            z1 += __shfl_sync(0xffffffffu, z, k) * sP1[k * 32 + lane];
        z1 = fmaxf(z1, 0.f);

        float z2 = sb2[lane];
#pragma unroll
        for (int k = 0; k < 32; k++)
            z2 += __shfl_sync(0xffffffffu, z1, k) * sP2[k * 32 + lane];
        z2 = fmaxf(z2, 0.f);

        float v = z2 * sP3[lane];
#pragma unroll
        for (int off = 16; off; off >>= 1)
            v += __shfl_down_sync(0xffffffffu, v, off);
        if (lane == 0) out[oi] = v + sb3;
    }
}

// ---------------------------------------------------------------------------
// Launch. Single stream (the round-4 multi-stream fork coincided with a
// container failure; reverted while keeping the kernel fusions).
// ---------------------------------------------------------------------------
extern "C" void kernel_launch(void* const* d_in, const int* in_sizes, int n_in,
                              void* d_out, int out_size) {
    const float* x    = (const float*)d_in[0];
    const int*   src  = (const int*)d_in[1];
    const int*   dst  = (const int*)d_in[2];
    const int*   nsr  = (const int*)d_in[3];
    const float* W0   = (const float*)d_in[4];
    const float* al0  = (const float*)d_in[5];
    const float* ar0  = (const float*)d_in[6];
    const float* b0   = (const float*)d_in[7];
    const float* W1   = (const float*)d_in[8];
    const float* al1  = (const float*)d_in[9];
    const float* ar1  = (const float*)d_in[10];
    const float* b1   = (const float*)d_in[11];
    const float* P1   = (const float*)d_in[12];
    const float* pb1  = (const float*)d_in[13];
    const float* P2   = (const float*)d_in[14];
    const float* pb2  = (const float*)d_in[15];
    const float* P3   = (const float*)d_in[16];
    const float* pb3  = (const float*)d_in[17];
    float* out = (float*)d_out;

    int N = in_sizes[0] / 128;
    int E = in_sizes[1];

    __half* p_f16; float *p_h0, *p_f1, *p_h1, *p_el0, *p_er0, *p_el1, *p_er1;
    int* p_cnt;
    cudaGetSymbolAddress((void**)&p_f16, g_f16);
    cudaGetSymbolAddress((void**)&p_h0,  g_h0);
    cudaGetSymbolAddress((void**)&p_f1,  g_f1);
    cudaGetSymbolAddress((void**)&p_h1,  g_h1);
    cudaGetSymbolAddress((void**)&p_el0, g_el0);
    cudaGetSymbolAddress((void**)&p_er0, g_er0);
    cudaGetSymbolAddress((void**)&p_el1, g_el1);
    cudaGetSymbolAddress((void**)&p_er1, g_er1);
    cudaGetSymbolAddress((void**)&p_cnt, g_cnt);

    int nbE = (E + 255) / 256;

    // 0..3: CSR build (memset counts -> hist -> scan -> fill)
    cudaMemsetAsync(p_cnt, 0, (size_t)N * sizeof(int), 0);
    k_hist<<<nbE, 256>>>(dst, E);
    k_scan<<<1, 1024>>>(N);
    k_fill<<<nbE, 256>>>(src, dst, E);

    // layer-0 GEMM (tf32, fused scores, fp16 feature output)
    {
        dim3 grid(F0DIM / 128, (N + 127) / 128);
        k_gemm_tf32<128, 4, 2, true><<<grid, 256>>>(x, W0, p_f16, al0, ar0,
                                                    p_el0, p_er0, N, F0DIM, 128, H0);
    }

    // layer-0 aggregation (fused weights, +elu)
    k_agg0<<<N, 128>>>(p_f16, p_el0, p_er0, b0, p_h0, N);

    // layer-1 GEMM -> aggregation (fused weights)
    {
        dim3 grid(DOUT / 32, (N + 127) / 128);
        k_gemm_tf32<32, 8, 1, false><<<grid, 256>>>(p_h0, W1, p_f1, al1, ar1,
                                                    p_el1, p_er1, N, DOUT, F0DIM, 1);
    }
    k_agg1<<<(N * 32 + 255) / 256, 256>>>(p_f1, p_el1, p_er1, b1, p_h1, N);

    // predictor
    k_predictor<<<512, 256>>>(p_h1, nsr, P1, pb1, P2, pb2, P3, pb3, out, N);
}